// round 8
// baseline (speedup 1.0000x reference)
#include <cuda_runtime.h>
#include <cuda_bf16.h>
#include <math.h>
#include <stdint.h>

#define BATCH 2
#define SEQ   2048
#define DM    2048
#define NH    16
#define DKH   128
#define MTOT  (BATCH*SEQ)   // 4096
#define BH    (BATCH*NH)    // 32

// ---- scratch (device globals) ----
__device__ float g_q[MTOT*DM];
__device__ float g_k[MTOT*DM];
__device__ float g_v[MTOT*DM];
__device__ float g_ctx[MTOT*DM];
// int8 GEMM operands
__device__ char  g_x8h[MTOT*DM];
__device__ char  g_x8l[MTOT*DM];
__device__ float g_sx[MTOT];
__device__ char  g_w8h[4][DM*DM];
__device__ char  g_w8l[4][DM*DM];
__device__ float g_swt[4][DM];
__device__ char  g_c8h[MTOT*DM];
__device__ char  g_c8l[MTOT*DM];
__device__ float g_sc2[MTOT];
// attention operands (bf16 hi/lo)
__device__ __nv_bfloat16 g_qh[BH*SEQ*DKH];
__device__ __nv_bfloat16 g_ql[BH*SEQ*DKH];
__device__ __nv_bfloat16 g_kh[BH*SEQ*DKH];
__device__ __nv_bfloat16 g_kl[BH*SEQ*DKH];
__device__ __nv_bfloat16 g_vth[BH*DKH*SEQ];
__device__ __nv_bfloat16 g_vtl[BH*DKH*SEQ];

// ============================================================
// helpers
// ============================================================
__device__ __forceinline__ uint32_t smem_u32(const void* p) {
    uint32_t a;
    asm("{ .reg .u64 t; cvta.to.shared.u64 t, %1; cvt.u32.u64 %0, t; }" : "=r"(a) : "l"(p));
    return a;
}
__device__ __forceinline__ void cp_async16(uint32_t dst, const void* src) {
    asm volatile("cp.async.cg.shared.global [%0], [%1], 16;" :: "r"(dst), "l"(src));
}
__device__ __forceinline__ void cp_commit() {
    asm volatile("cp.async.commit_group;" ::: "memory");
}
template<int N>
__device__ __forceinline__ void cp_wait() {
    asm volatile("cp.async.wait_group %0;" :: "n"(N) : "memory");
}
__device__ __forceinline__ void ldsm_x4(uint32_t& r0, uint32_t& r1, uint32_t& r2, uint32_t& r3, uint32_t a) {
    asm volatile("ldmatrix.sync.aligned.m8n8.x4.shared.b16 {%0,%1,%2,%3}, [%4];"
                 : "=r"(r0), "=r"(r1), "=r"(r2), "=r"(r3) : "r"(a));
}
__device__ __forceinline__ void ldsm_x2(uint32_t& r0, uint32_t& r1, uint32_t a) {
    asm volatile("ldmatrix.sync.aligned.m8n8.x2.shared.b16 {%0,%1}, [%2];"
                 : "=r"(r0), "=r"(r1) : "r"(a));
}
__device__ __forceinline__ void mma_bf16(float* c, const uint32_t* a, const uint32_t* b) {
    asm volatile("mma.sync.aligned.m16n8k16.row.col.f32.bf16.bf16.f32 "
                 "{%0,%1,%2,%3}, {%4,%5,%6,%7}, {%8,%9}, {%0,%1,%2,%3};"
                 : "+f"(c[0]), "+f"(c[1]), "+f"(c[2]), "+f"(c[3])
                 : "r"(a[0]), "r"(a[1]), "r"(a[2]), "r"(a[3]), "r"(b[0]), "r"(b[1]));
}
__device__ __forceinline__ void mma_s8(int* c, const uint32_t* a, const uint32_t* b) {
    asm volatile("mma.sync.aligned.m16n8k32.row.col.s32.s8.s8.s32 "
                 "{%0,%1,%2,%3}, {%4,%5,%6,%7}, {%8,%9}, {%0,%1,%2,%3};"
                 : "+r"(c[0]), "+r"(c[1]), "+r"(c[2]), "+r"(c[3])
                 : "r"(a[0]), "r"(a[1]), "r"(a[2]), "r"(a[3]), "r"(b[0]), "r"(b[1]));
}
__device__ __forceinline__ uint32_t pack_bf2(float x, float y) {
    __nv_bfloat162 t(__float2bfloat16(x), __float2bfloat16(y));
    return *(uint32_t*)&t;
}

// ============================================================
// Row quantize: fp32 row (2048) -> two s8 limbs + per-row scale
// a16 = round(x * 32512/max);  h = (a16+128)>>8;  l = a16 - h*256
// ============================================================
__global__ __launch_bounds__(256)
void quant_rows(const float* __restrict__ src, char* __restrict__ hi,
                char* __restrict__ lo, float* __restrict__ scale)
{
    __shared__ float red[8];
    int row = blockIdx.x;
    int tid = threadIdx.x, wid = tid >> 5, lane = tid & 31;
    const float* s = src + (size_t)row * DM;
    int base = tid * 8;
    float4 v0 = *(const float4*)(s + base);
    float4 v1 = *(const float4*)(s + base + 4);
    float vals[8] = {v0.x, v0.y, v0.z, v0.w, v1.x, v1.y, v1.z, v1.w};
    float mx = 0.f;
#pragma unroll
    for (int j = 0; j < 8; ++j) mx = fmaxf(mx, fabsf(vals[j]));
#pragma unroll
    for (int off = 16; off >= 1; off >>= 1)
        mx = fmaxf(mx, __shfl_xor_sync(0xffffffffu, mx, off));
    if (lane == 0) red[wid] = mx;
    __syncthreads();
    mx = red[0];
#pragma unroll
    for (int i = 1; i < 8; ++i) mx = fmaxf(mx, red[i]);
    float inv = (mx > 0.f) ? 32512.f / mx : 0.f;
    if (tid == 0) scale[row] = (mx > 0.f) ? mx / 32512.f : 0.f;

    char h8[8], l8[8];
#pragma unroll
    for (int j = 0; j < 8; ++j) {
        int a16 = __float2int_rn(vals[j] * inv);
        int h = (a16 + 128) >> 8;
        int l = a16 - (h << 8);
        h8[j] = (char)h; l8[j] = (char)l;
    }
    char4* hp = (char4*)(hi + (size_t)row*DM + base);
    char4* lp = (char4*)(lo + (size_t)row*DM + base);
    hp[0] = make_char4(h8[0],h8[1],h8[2],h8[3]);
    hp[1] = make_char4(h8[4],h8[5],h8[6],h8[7]);
    lp[0] = make_char4(l8[0],l8[1],l8[2],l8[3]);
    lp[1] = make_char4(l8[4],l8[5],l8[6],l8[7]);
}

// ============================================================
// int8 GEMM: C[M,N] = A[M,K] @ W[N,K]^T, limb-split s8 IMMA.
// BM=BN=128, BK=32, 256 thr (8 warps 2x4), warp 64x32.
// smem rows 48B stride (conflict-free ldmatrix).
// ============================================================
#define IBK 32
#define ISTR 48
#define ITILE (128*ISTR)      // 6144
#define ISTAGE (4*ITILE)      // 24576
#define IGEMM_SMEM (2*ISTAGE) // 49152

template<int ADD_BIAS>
__global__ __launch_bounds__(256, 1)
void gemm_i8(const char* __restrict__ Ah, const char* __restrict__ Al,
             const char* __restrict__ Bh, const char* __restrict__ Bl,
             const float* __restrict__ sa, const float* __restrict__ sw,
             const float* __restrict__ bias, float* __restrict__ C)
{
    extern __shared__ __align__(128) char gsm[];
    const uint32_t sb = smem_u32(gsm);
    const int tid = threadIdx.x, wid = tid >> 5, lane = tid & 31;
    const int bm = blockIdx.y * 128;
    const int bn = blockIdx.x * 128;
    const int warp_m = wid >> 2;     // 0..1
    const int warp_n = wid & 3;      // 0..3
    const uint32_t OFF_AH = 0, OFF_AL = ITILE, OFF_BH = 2*ITILE, OFF_BL = 3*ITILE;

    int hh[4][4][4], cr[4][4][4];
#pragma unroll
    for (int i = 0; i < 4; i++)
#pragma unroll
        for (int j = 0; j < 4; j++)
#pragma unroll
            for (int r = 0; r < 4; r++) { hh[i][j][r] = 0; cr[i][j][r] = 0; }

    const int lrow = tid >> 1;
    const int lseg = (tid & 1) * 16;
    auto issue = [&](int c, int buf) {
        uint32_t st = sb + buf * ISTAGE;
        int k0 = c * IBK;
        uint32_t dst = (uint32_t)(lrow * ISTR + lseg);
        cp_async16(st + OFF_AH + dst, Ah + (size_t)(bm + lrow)*DM + k0 + lseg);
        cp_async16(st + OFF_AL + dst, Al + (size_t)(bm + lrow)*DM + k0 + lseg);
        cp_async16(st + OFF_BH + dst, Bh + (size_t)(bn + lrow)*DM + k0 + lseg);
        cp_async16(st + OFF_BL + dst, Bl + (size_t)(bn + lrow)*DM + k0 + lseg);
        cp_commit();
    };

    issue(0, 0);

    const uint32_t a_base = (uint32_t)((warp_m*64 + (lane & 15)) * ISTR + (lane >> 4) * 16);
    const uint32_t b_base = (uint32_t)((warp_n*32 + (lane & 7)) * ISTR + ((lane >> 3) & 1) * 16);

    const int NCH = DM / IBK;    // 64
    for (int c = 0; c < NCH; ++c) {
        int buf = c & 1;
        if (c + 1 < NCH) { issue(c + 1, buf ^ 1); cp_wait<1>(); }
        else             { cp_wait<0>(); }
        __syncthreads();

        uint32_t st = sb + buf * ISTAGE;
        uint32_t Af[4][4], Alf[4][4];
#pragma unroll
        for (int am = 0; am < 4; ++am) {
            ldsm_x4(Af[am][0], Af[am][1], Af[am][2], Af[am][3],
                    st + OFF_AH + a_base + am*16*ISTR);
            ldsm_x4(Alf[am][0], Alf[am][1], Alf[am][2], Alf[am][3],
                    st + OFF_AL + a_base + am*16*ISTR);
        }
#pragma unroll
        for (int bt = 0; bt < 4; ++bt) {
            uint32_t bhf[2], blf[2];
            ldsm_x2(bhf[0], bhf[1], st + OFF_BH + b_base + bt*8*ISTR);
            ldsm_x2(blf[0], blf[1], st + OFF_BL + b_base + bt*8*ISTR);
#pragma unroll
            for (int am = 0; am < 4; ++am) {
                mma_s8(hh[am][bt], Af[am],  bhf);
                mma_s8(cr[am][bt], Af[am],  blf);
                mma_s8(cr[am][bt], Alf[am], bhf);
            }
        }
        __syncthreads();
    }

    const int m_base = bm + warp_m*64;
    const int n_base = bn + warp_n*32;
#pragma unroll
    for (int am = 0; am < 4; ++am) {
        int r0 = m_base + am*16 + (lane >> 2);
        float s0 = sa[r0], s1 = sa[r0 + 8];
#pragma unroll
        for (int bt = 0; bt < 4; ++bt) {
            int col = n_base + bt*8 + (lane & 3)*2;
            float w0 = sw[col], w1 = sw[col + 1];
            float b0 = 0.f, b1 = 0.f;
            if (ADD_BIAS) { b0 = bias[col]; b1 = bias[col + 1]; }
            float v00 = ((float)hh[am][bt][0]*65536.f + (float)cr[am][bt][0]*256.f)*s0*w0 + b0;
            float v01 = ((float)hh[am][bt][1]*65536.f + (float)cr[am][bt][1]*256.f)*s0*w1 + b1;
            float v10 = ((float)hh[am][bt][2]*65536.f + (float)cr[am][bt][2]*256.f)*s1*w0 + b0;
            float v11 = ((float)hh[am][bt][3]*65536.f + (float)cr[am][bt][3]*256.f)*s1*w1 + b1;
            *(float2*)(C + (size_t)r0*DM + col)     = make_float2(v00, v01);
            *(float2*)(C + (size_t)(r0+8)*DM + col) = make_float2(v10, v11);
        }
    }
}

// ============================================================
// RoPE + split: fp32 q,k [b][s][h*128+dk] -> bf16 hi/lo [bh][s][dk]
// ============================================================
__global__ __launch_bounds__(256)
void rope_split_kernel()
{
    int idx = blockIdx.x * blockDim.x + threadIdx.x;
    const int total = BH*SEQ*64;
    if (idx >= total) return;
    int i  = idx & 63;
    int s  = (idx >> 6) & (SEQ-1);
    int bh = idx >> 17;
    int b = bh >> 4, h = bh & 15;
    size_t src = ((size_t)b*SEQ + s)*DM + h*DKH + 2*i;
    size_t dst = ((size_t)bh*SEQ + s)*DKH + 2*i;

    float freq = powf(10000.f, -((float)(2*i)) / 128.f);
    float ang  = (float)s * freq;
    float sn, cs;
    sincosf(ang, &sn, &cs);

    float qe = g_q[src], qo = g_q[src+1];
    float q0 = qe*cs - qo*sn, q1 = qe*sn + qo*cs;
    float ke = g_k[src], ko = g_k[src+1];
    float k0 = ke*cs - ko*sn, k1 = ke*sn + ko*cs;

    __nv_bfloat16 qh0 = __float2bfloat16(q0), qh1 = __float2bfloat16(q1);
    __nv_bfloat16 kh0 = __float2bfloat16(k0), kh1 = __float2bfloat16(k1);
    *(__nv_bfloat162*)&g_qh[dst] = __nv_bfloat162(qh0, qh1);
    *(__nv_bfloat162*)&g_ql[dst] = __nv_bfloat162(
        __float2bfloat16(q0 - __bfloat162float(qh0)),
        __float2bfloat16(q1 - __bfloat162float(qh1)));
    *(__nv_bfloat162*)&g_kh[dst] = __nv_bfloat162(kh0, kh1);
    *(__nv_bfloat162*)&g_kl[dst] = __nv_bfloat162(
        __float2bfloat16(k0 - __bfloat162float(kh0)),
        __float2bfloat16(k1 - __bfloat162float(kh1)));
}

// ============================================================
// V transpose+split: fp32 v [b][s][h*128+dk] -> bf16 [bh][dk][s]
// ============================================================
__global__ __launch_bounds__(256)
void vsplit_kernel()
{
    __shared__ float t[32][33];
    int dk0 = blockIdx.x * 32;
    int s0  = blockIdx.y * 32;
    int bh  = blockIdx.z;
    int b = bh >> 4, h = bh & 15;
    int tx = threadIdx.x & 31, ty = threadIdx.x >> 5;
#pragma unroll
    for (int r = 0; r < 4; ++r)
        t[ty + 8*r][tx] = g_v[((size_t)(b*SEQ) + s0 + ty + 8*r)*DM + h*DKH + dk0 + tx];
    __syncthreads();
#pragma unroll
    for (int r = 0; r < 4; ++r) {
        int dk = ty + 8*r;
        float val = t[tx][dk];
        __nv_bfloat16 hi = __float2bfloat16(val);
        size_t dst = ((size_t)bh*DKH + dk0 + dk)*SEQ + s0 + tx;
        g_vth[dst] = hi;
        g_vtl[dst] = __float2bfloat16(val - __bfloat162float(hi));
    }
}

// ============================================================
// Flash attention, bf16 mma, causal.  longest-first qt order.
// ============================================================
#define KSTRB 272
#define VSTRB 144
#define AQH 0
#define AQL 34816
#define AST0 69632
#define ASTAGE 71680
#define AKH 0
#define AKL 17408
#define AVTH 34816
#define AVTL 53248
#define ATTN_SMEM (AST0 + 2*ASTAGE)    // 212992

__global__ __launch_bounds__(256, 1)
void attn_mma(const __nv_bfloat16* __restrict__ qh, const __nv_bfloat16* __restrict__ ql,
              const __nv_bfloat16* __restrict__ kh, const __nv_bfloat16* __restrict__ kl,
              const __nv_bfloat16* __restrict__ vth, const __nv_bfloat16* __restrict__ vtl,
              float* __restrict__ ctx)
{
    extern __shared__ __align__(128) char asm_[];
    const uint32_t sb = smem_u32(asm_);
    const int qt = (gridDim.x - 1) - blockIdx.x;   // longest CTAs scheduled first
    const int bh = blockIdx.y;
    const int tid = threadIdx.x, warp = tid >> 5, lane = tid & 31;
    const int b = bh >> 4, h = bh & 15;

    const __nv_bfloat16* qhb = qh + ((size_t)bh*SEQ + qt*128)*DKH;
    const __nv_bfloat16* qlb = ql + ((size_t)bh*SEQ + qt*128)*DKH;
    const __nv_bfloat16* khb = kh + (size_t)bh*SEQ*DKH;
    const __nv_bfloat16* klb = kl + (size_t)bh*SEQ*DKH;
    const __nv_bfloat16* vhb = vth + (size_t)bh*DKH*SEQ;
    const __nv_bfloat16* vlb = vtl + (size_t)bh*DKH*SEQ;

    for (int i = tid; i < 2048; i += 256) {
        int row = i >> 4, seg = i & 15;
        uint32_t dst = (uint32_t)(row * KSTRB + seg * 16);
        cp_async16(sb + AQH + dst, (const char*)(qhb + (size_t)row*DKH) + seg*16);
        cp_async16(sb + AQL + dst, (const char*)(qlb + (size_t)row*DKH) + seg*16);
    }
    cp_commit();

    auto issue_kv = [&](int kt, int buf) {
        uint32_t st = sb + AST0 + buf * ASTAGE;
        for (int i = tid; i < 1024; i += 256) {
            int row = i >> 4, seg = i & 15;
            uint32_t dst = (uint32_t)(row * KSTRB + seg * 16);
            cp_async16(st + AKH + dst, (const char*)(khb + ((size_t)(kt*64) + row)*DKH) + seg*16);
            cp_async16(st + AKL + dst, (const char*)(klb + ((size_t)(kt*64) + row)*DKH) + seg*16);
        }
        for (int i = tid; i < 1024; i += 256) {
            int row = i >> 3, seg = i & 7;
            uint32_t dst = (uint32_t)(row * VSTRB + seg * 16);
            cp_async16(st + AVTH + dst, (const char*)(vhb + (size_t)row*SEQ + kt*64) + seg*16);
            cp_async16(st + AVTL + dst, (const char*)(vlb + (size_t)row*SEQ + kt*64) + seg*16);
        }
        cp_commit();
    };

    const int nkt = 2*qt + 2;
    issue_kv(0, 0);

    float o[16][4];
#pragma unroll
    for (int i = 0; i < 16; i++)
#pragma unroll
        for (int j = 0; j < 4; j++) o[i][j] = 0.f;
    float m_[2] = {-1e30f, -1e30f};
    float l_[2] = {0.f, 0.f};

    const float scl = 0.08838834764831845f;
    const int row0g = qt*128 + warp*16 + (lane >> 2);

    const uint32_t a_off = (uint32_t)((warp*16 + (lane & 15)) * KSTRB + (lane >> 4) * 16);
    const uint32_t kb_rowsel = (uint32_t)((((lane >> 3) & 1) * 8 + (lane & 7)));
    const uint32_t kseg = (uint32_t)((lane >> 4) * 16);

    for (int kt = 0; kt < nkt; ++kt) {
        int buf = kt & 1;
        if (kt + 1 < nkt) { issue_kv(kt + 1, buf ^ 1); cp_wait<1>(); }
        else              { cp_wait<0>(); }
        __syncthreads();

        uint32_t st = sb + AST0 + buf * ASTAGE;

        float s_[8][4];
#pragma unroll
        for (int i = 0; i < 8; i++)
#pragma unroll
            for (int j = 0; j < 4; j++) s_[i][j] = 0.f;

#pragma unroll
        for (int ks = 0; ks < 8; ++ks) {
            uint32_t aH[4], aL[4];
            ldsm_x4(aH[0], aH[1], aH[2], aH[3], sb + AQH + a_off + ks*32);
            ldsm_x4(aL[0], aL[1], aL[2], aL[3], sb + AQL + a_off + ks*32);
#pragma unroll
            for (int p = 0; p < 4; ++p) {
                uint32_t kaddr = st + (uint32_t)((p*16 + kb_rowsel) * KSTRB) + ks*32 + kseg;
                uint32_t r0, r1, r2, r3;
                ldsm_x4(r0, r1, r2, r3, kaddr + AKH);
                uint32_t bh0[2] = {r0, r2}, bh1[2] = {r1, r3};
                mma_bf16(s_[2*p],   aH, bh0);
                mma_bf16(s_[2*p+1], aH, bh1);
                mma_bf16(s_[2*p],   aL, bh0);
                mma_bf16(s_[2*p+1], aL, bh1);
                ldsm_x4(r0, r1, r2, r3, kaddr + AKL);
                uint32_t bl0[2] = {r0, r2}, bl1[2] = {r1, r3};
                mma_bf16(s_[2*p],   aH, bl0);
                mma_bf16(s_[2*p+1], aH, bl1);
            }
        }

        bool need_mask = (kt*64 + 63) > (qt*128 + warp*16);
#pragma unroll
        for (int nt = 0; nt < 8; ++nt) {
            int colg = kt*64 + nt*8 + (lane & 3)*2;
#pragma unroll
            for (int j = 0; j < 4; ++j) {
                float sv = s_[nt][j] * scl;
                if (need_mask) {
                    int r = row0g + ((j >> 1) << 3);
                    int c = colg + (j & 1);
                    if (c > r) sv = -1e30f;
                }
                s_[nt][j] = sv;
            }
        }

        float corr[2];
#pragma unroll
        for (int r = 0; r < 2; ++r) {
            float mx = m_[r];
#pragma unroll
            for (int nt = 0; nt < 8; ++nt)
                mx = fmaxf(mx, fmaxf(s_[nt][2*r], s_[nt][2*r+1]));
            mx = fmaxf(mx, __shfl_xor_sync(0xffffffffu, mx, 1));
            mx = fmaxf(mx, __shfl_xor_sync(0xffffffffu, mx, 2));
            corr[r] = __expf(m_[r] - mx);
            m_[r] = mx;
            float sum = 0.f;
#pragma unroll
            for (int nt = 0; nt < 8; ++nt) {
                float p0 = __expf(s_[nt][2*r]   - mx);
                float p1 = __expf(s_[nt][2*r+1] - mx);
                s_[nt][2*r] = p0; s_[nt][2*r+1] = p1;
                sum += p0 + p1;
            }
            sum += __shfl_xor_sync(0xffffffffu, sum, 1);
            sum += __shfl_xor_sync(0xffffffffu, sum, 2);
            l_[r] = l_[r]*corr[r] + sum;
        }

        uint32_t pH[8][2], pL[8][2];
#pragma unroll
        for (int nt = 0; nt < 8; ++nt) {
#pragma unroll
            for (int r = 0; r < 2; ++r) {
                float p0 = s_[nt][2*r], p1 = s_[nt][2*r+1];
                __nv_bfloat16 h0 = __float2bfloat16(p0), h1 = __float2bfloat16(p1);
                pH[nt][r] = pack_bf2(p0, p1);
                pL[nt][r] = pack_bf2(p0 - __bfloat162float(h0), p1 - __bfloat162float(h1));
            }
        }

#pragma unroll
        for (int dt = 0; dt < 16; ++dt) {
            o[dt][0] *= corr[0]; o[dt][1] *= corr[0];
            o[dt][2] *= corr[1]; o[dt][3] *= corr[1];
        }

#pragma unroll
        for (int kk = 0; kk < 4; ++kk) {
            uint32_t aP[4]  = {pH[2*kk][0], pH[2*kk][1], pH[2*kk+1][0], pH[2*kk+1][1]};
            uint32_t aPl[4] = {pL[2*kk][0], pL[2*kk][1], pL[2*kk+1][0], pL[2*kk+1][1]};
#pragma unroll
            for (int p = 0; p < 8; ++p) {
                uint32_t vaddr = st + (uint32_t)((p*16 + kb_rowsel) * VSTRB) + kk*32 + kseg;
                uint32_t r0, r1, r2, r3;
                ldsm_x4(r0, r1, r2, r3, vaddr + AVTH);
                uint32_t vh0[2] = {r0, r2}, vh1[2] = {r1, r3};
                mma_bf16(o[2*p],   aP,  vh0);
                mma_bf16(o[2*p+1], aP,  vh1);
                mma_bf16(o[2*p],   aPl, vh0);
                mma_bf16(o[2*p+1], aPl, vh1);
                ldsm_x4(r0, r1, r2, r3, vaddr + AVTL);
                uint32_t vl0[2] = {r0, r2}, vl1[2] = {r1, r3};
                mma_bf16(o[2*p],   aP, vl0);
                mma_bf16(o[2*p+1], aP, vl1);
            }
        }
        __syncthreads();
    }

    float inv0 = 1.0f / l_[0], inv1 = 1.0f / l_[1];
    int r0 = qt*128 + warp*16 + (lane >> 2);
#pragma unroll
    for (int dt = 0; dt < 16; ++dt) {
        int col = h*DKH + dt*8 + (lane & 3)*2;
        *(float2*)&ctx[((size_t)(b*SEQ) + r0)*DM + col] =
            make_float2(o[dt][0]*inv0, o[dt][1]*inv0);
        *(float2*)&ctx[((size_t)(b*SEQ) + r0 + 8)*DM + col] =
            make_float2(o[dt][2]*inv1, o[dt][3]*inv1);
    }
}

// ============================================================
extern "C" void kernel_launch(void* const* d_in, const int* in_sizes, int n_in,
                              void* d_out, int out_size)
{
    const float* x  = (const float*)d_in[0];
    const float* wq = (const float*)d_in[1];
    const float* wk = (const float*)d_in[2];
    const float* wv = (const float*)d_in[3];
    const float* wo = (const float*)d_in[4];
    const float* bo = (const float*)d_in[5];
    float* out = (float*)d_out;

    float *q, *k, *v, *ctx, *sx, *swt, *sc;
    char *x8h, *x8l, *w8h, *w8l, *c8h, *c8l;
    __nv_bfloat16 *qh, *ql, *kh, *kl, *vth, *vtl;
    cudaGetSymbolAddress((void**)&q,   g_q);
    cudaGetSymbolAddress((void**)&k,   g_k);
    cudaGetSymbolAddress((void**)&v,   g_v);
    cudaGetSymbolAddress((void**)&ctx, g_ctx);
    cudaGetSymbolAddress((void**)&x8h, g_x8h);
    cudaGetSymbolAddress((void**)&x8l, g_x8l);
    cudaGetSymbolAddress((void**)&sx,  g_sx);
    cudaGetSymbolAddress((void**)&w8h, g_w8h);
    cudaGetSymbolAddress((void**)&w8l, g_w8l);
    cudaGetSymbolAddress((void**)&swt, g_swt);
    cudaGetSymbolAddress((void**)&c8h, g_c8h);
    cudaGetSymbolAddress((void**)&c8l, g_c8l);
    cudaGetSymbolAddress((void**)&sc,  g_sc2);
    cudaGetSymbolAddress((void**)&qh,  g_qh);
    cudaGetSymbolAddress((void**)&ql,  g_ql);
    cudaGetSymbolAddress((void**)&kh,  g_kh);
    cudaGetSymbolAddress((void**)&kl,  g_kl);
    cudaGetSymbolAddress((void**)&vth, g_vth);
    cudaGetSymbolAddress((void**)&vtl, g_vtl);

    cudaFuncSetAttribute(gemm_i8<0>, cudaFuncAttributeMaxDynamicSharedMemorySize, IGEMM_SMEM);
    cudaFuncSetAttribute(gemm_i8<1>, cudaFuncAttributeMaxDynamicSharedMemorySize, IGEMM_SMEM);
    cudaFuncSetAttribute(attn_mma, cudaFuncAttributeMaxDynamicSharedMemorySize, ATTN_SMEM);

    // quantize x and weights
    quant_rows<<<MTOT, 256>>>(x, x8h, x8l, sx);
    quant_rows<<<DM, 256>>>(wq, w8h + 0*(size_t)DM*DM, w8l + 0*(size_t)DM*DM, swt + 0*DM);
    quant_rows<<<DM, 256>>>(wk, w8h + 1*(size_t)DM*DM, w8l + 1*(size_t)DM*DM, swt + 1*DM);
    quant_rows<<<DM, 256>>>(wv, w8h + 2*(size_t)DM*DM, w8l + 2*(size_t)DM*DM, swt + 2*DM);
    quant_rows<<<DM, 256>>>(wo, w8h + 3*(size_t)DM*DM, w8l + 3*(size_t)DM*DM, swt + 3*DM);

    dim3 gg(DM/128, MTOT/128);   // (16, 32)
    gemm_i8<0><<<gg, 256, IGEMM_SMEM>>>(x8h, x8l, w8h + 0*(size_t)DM*DM, w8l + 0*(size_t)DM*DM, sx, swt + 0*DM, nullptr, q);
    gemm_i8<0><<<gg, 256, IGEMM_SMEM>>>(x8h, x8l, w8h + 1*(size_t)DM*DM, w8l + 1*(size_t)DM*DM, sx, swt + 1*DM, nullptr, k);
    gemm_i8<0><<<gg, 256, IGEMM_SMEM>>>(x8h, x8l, w8h + 2*(size_t)DM*DM, w8l + 2*(size_t)DM*DM, sx, swt + 2*DM, nullptr, v);

    rope_split_kernel<<<(BH*SEQ*64 + 255)/256, 256>>>();
    vsplit_kernel<<<dim3(DKH/32, SEQ/32, BH), 256>>>();

    attn_mma<<<dim3(SEQ/128, BH), 256, ATTN_SMEM>>>(qh, ql, kh, kl, vth, vtl, ctx);

    quant_rows<<<MTOT, 256>>>(ctx, c8h, c8l, sc);
    gemm_i8<1><<<gg, 256, IGEMM_SMEM>>>(c8h, c8l, w8h + 3*(size_t)DM*DM, w8l + 3*(size_t)DM*DM, sc, swt + 3*DM, bo, out);
}

// round 11
// speedup vs baseline: 3.9459x; 3.9459x over previous
#include <cuda_runtime.h>
#include <cuda_fp16.h>
#include <math.h>
#include <stdint.h>

#define BATCH 2
#define SEQ   2048
#define DM    2048
#define NH    16
#define DKH   128
#define MTOT  (BATCH*SEQ)   // 4096
#define BH    (BATCH*NH)    // 32

// ---- scratch (device globals) ----
__device__ float g_q[MTOT*DM];
__device__ float g_k[MTOT*DM];
__device__ float g_v[MTOT*DM];
__device__ float g_ctx[MTOT*DM];
__device__ __half g_x16[MTOT*DM];
__device__ __half g_w16[4][DM*DM];
__device__ __half g_c16[MTOT*DM];
// attention operands
__device__ __half g_qh[BH*SEQ*DKH];
__device__ __half g_ql[BH*SEQ*DKH];
__device__ __half g_kh[BH*SEQ*DKH];
__device__ __half g_vth[BH*DKH*SEQ];

// ============================================================
// helpers
// ============================================================
__device__ __forceinline__ uint32_t smem_u32(const void* p) {
    uint32_t a;
    asm("{ .reg .u64 t; cvta.to.shared.u64 t, %1; cvt.u32.u64 %0, t; }" : "=r"(a) : "l"(p));
    return a;
}
__device__ __forceinline__ void cp_async16(uint32_t dst, const void* src) {
    asm volatile("cp.async.cg.shared.global [%0], [%1], 16;" :: "r"(dst), "l"(src));
}
__device__ __forceinline__ void cp_commit() {
    asm volatile("cp.async.commit_group;" ::: "memory");
}
template<int N>
__device__ __forceinline__ void cp_wait() {
    asm volatile("cp.async.wait_group %0;" :: "n"(N) : "memory");
}
__device__ __forceinline__ void ldsm_x4(uint32_t& r0, uint32_t& r1, uint32_t& r2, uint32_t& r3, uint32_t a) {
    asm volatile("ldmatrix.sync.aligned.m8n8.x4.shared.b16 {%0,%1,%2,%3}, [%4];"
                 : "=r"(r0), "=r"(r1), "=r"(r2), "=r"(r3) : "r"(a));
}
__device__ __forceinline__ void ldsm_x2(uint32_t& r0, uint32_t& r1, uint32_t a) {
    asm volatile("ldmatrix.sync.aligned.m8n8.x2.shared.b16 {%0,%1}, [%2];"
                 : "=r"(r0), "=r"(r1) : "r"(a));
}
__device__ __forceinline__ void mma_f16(float* c, const uint32_t* a, const uint32_t* b) {
    asm volatile("mma.sync.aligned.m16n8k16.row.col.f32.f16.f16.f32 "
                 "{%0,%1,%2,%3}, {%4,%5,%6,%7}, {%8,%9}, {%0,%1,%2,%3};"
                 : "+f"(c[0]), "+f"(c[1]), "+f"(c[2]), "+f"(c[3])
                 : "r"(a[0]), "r"(a[1]), "r"(a[2]), "r"(a[3]), "r"(b[0]), "r"(b[1]));
}
__device__ __forceinline__ uint32_t pack_h2(float x, float y) {
    __half2 t(__float2half(x), __float2half(y));
    return *(uint32_t*)&t;
}

// ============================================================
// Convert fp32 -> fp16
// ============================================================
__global__ __launch_bounds__(256)
void tohalf_kernel(const float* __restrict__ src, __half* __restrict__ dst, int n4)
{
    int i = blockIdx.x * 256 + threadIdx.x;
    if (i >= n4) return;
    float4 v = ((const float4*)src)[i];
    __half2 h0(__float2half(v.x), __float2half(v.y));
    __half2 h1(__float2half(v.z), __float2half(v.w));
    ((__half2*)dst)[2*i]   = h0;
    ((__half2*)dst)[2*i+1] = h1;
}

// ============================================================
// fp16 single-pass GEMM: C[M,N] = A[M,K] @ W[N,K]^T
// BM=BN=128, BK=32, 256 thr (8 warps 2x4), warp 64x32.
// smem rows 80B stride (conflict-free ldmatrix).
// ============================================================
#define BK 32
#define GSTR 80                      // bytes per smem row (64 data + 16 pad)
#define GTILE (128*GSTR)             // 10240
#define GSTAGE (2*GTILE)             // 20480: A, B
#define GEMM_SMEM (2*GSTAGE)         // 40960

template<int ADD_BIAS>
__global__ __launch_bounds__(256, 2)
void gemm_f16(const __half* __restrict__ A, const __half* __restrict__ B,
              const float* __restrict__ bias, float* __restrict__ C)
{
    extern __shared__ __align__(128) char gsm[];
    const uint32_t sb = smem_u32(gsm);
    const int tid = threadIdx.x, wid = tid >> 5, lane = tid & 31;
    const int bm = blockIdx.y * 128;
    const int bn = blockIdx.x * 128;
    const int warp_m = wid >> 2;
    const int warp_n = wid & 3;
    const uint32_t OFF_A = 0, OFF_B = GTILE;

    float acc[4][4][4];
#pragma unroll
    for (int i = 0; i < 4; i++)
#pragma unroll
        for (int j = 0; j < 4; j++)
#pragma unroll
            for (int r = 0; r < 4; r++) acc[i][j][r] = 0.f;

    auto issue = [&](int c, int buf) {
        uint32_t st = sb + buf * GSTAGE;
        int k0 = c * BK;
#pragma unroll
        for (int t = 0; t < 2; ++t) {
            int i = tid * 2 + t;
            int row = i >> 2, seg = i & 3;
            uint32_t dst = (uint32_t)(row * GSTR + seg * 16);
            cp_async16(st + OFF_A + dst, (const char*)(A + (size_t)(bm + row)*DM + k0) + seg*16);
            cp_async16(st + OFF_B + dst, (const char*)(B + (size_t)(bn + row)*DM + k0) + seg*16);
        }
        cp_commit();
    };

    issue(0, 0);

    const uint32_t a_base = (uint32_t)((warp_m*64 + (lane & 15)) * GSTR + (lane >> 4) * 16);
    const uint32_t b_base = (uint32_t)((warp_n*32 + (lane & 7)) * GSTR + ((lane >> 3) & 1) * 16);

    const int NCH = DM / BK;    // 64
    for (int c = 0; c < NCH; ++c) {
        int buf = c & 1;
        if (c + 1 < NCH) { issue(c + 1, buf ^ 1); cp_wait<1>(); }
        else             { cp_wait<0>(); }
        __syncthreads();

        uint32_t st = sb + buf * GSTAGE;
#pragma unroll
        for (int kk = 0; kk < 2; ++kk) {
            uint32_t af[4][4], bf[4][2];
#pragma unroll
            for (int am = 0; am < 4; ++am)
                ldsm_x4(af[am][0], af[am][1], af[am][2], af[am][3],
                        st + OFF_A + a_base + am*16*GSTR + kk*32);
#pragma unroll
            for (int bt = 0; bt < 4; ++bt)
                ldsm_x2(bf[bt][0], bf[bt][1], st + OFF_B + b_base + bt*8*GSTR + kk*32);
#pragma unroll
            for (int am = 0; am < 4; ++am)
#pragma unroll
                for (int bt = 0; bt < 4; ++bt)
                    mma_f16(acc[am][bt], af[am], bf[bt]);
        }
        __syncthreads();
    }

    const int m_base = bm + warp_m*64;
    const int n_base = bn + warp_n*32;
#pragma unroll
    for (int am = 0; am < 4; ++am) {
#pragma unroll
        for (int bt = 0; bt < 4; ++bt) {
            int col = n_base + bt*8 + (lane & 3)*2;
            int r0 = m_base + am*16 + (lane >> 2);
            float b0 = 0.f, b1 = 0.f;
            if (ADD_BIAS) { b0 = bias[col]; b1 = bias[col+1]; }
            *(float2*)(C + (size_t)r0*DM + col) =
                make_float2(acc[am][bt][0] + b0, acc[am][bt][1] + b1);
            *(float2*)(C + (size_t)(r0+8)*DM + col) =
                make_float2(acc[am][bt][2] + b0, acc[am][bt][3] + b1);
        }
    }
}

// ============================================================
// RoPE + split: fp32 q,k [b][s][h*128+dk] -> Qh,Ql fp16 + K fp16, [bh][s][dk]
// ============================================================
__global__ __launch_bounds__(256)
void rope_split_kernel()
{
    int idx = blockIdx.x * blockDim.x + threadIdx.x;
    const int total = BH*SEQ*64;
    if (idx >= total) return;
    int i  = idx & 63;
    int s  = (idx >> 6) & (SEQ-1);
    int bh = idx >> 17;
    int b = bh >> 4, h = bh & 15;
    size_t src = ((size_t)b*SEQ + s)*DM + h*DKH + 2*i;
    size_t dst = ((size_t)bh*SEQ + s)*DKH + 2*i;

    float freq = powf(10000.f, -((float)(2*i)) / 128.f);
    float ang  = (float)s * freq;
    float sn, cs;
    sincosf(ang, &sn, &cs);

    float qe = g_q[src], qo = g_q[src+1];
    float q0 = qe*cs - qo*sn, q1 = qe*sn + qo*cs;
    float ke = g_k[src], ko = g_k[src+1];
    float k0 = ke*cs - ko*sn, k1 = ke*sn + ko*cs;

    __half qh0 = __float2half(q0), qh1 = __float2half(q1);
    *(__half2*)&g_qh[dst] = __half2(qh0, qh1);
    *(__half2*)&g_ql[dst] = __half2(__float2half(q0 - __half2float(qh0)),
                                    __float2half(q1 - __half2float(qh1)));
    *(__half2*)&g_kh[dst] = __half2(__float2half(k0), __float2half(k1));
}

// ============================================================
// V transpose: fp32 v [b][s][h*128+dk] -> fp16 [bh][dk][s]
// ============================================================
__global__ __launch_bounds__(256)
void vsplit_kernel()
{
    __shared__ float t[32][33];
    int dk0 = blockIdx.x * 32;
    int s0  = blockIdx.y * 32;
    int bh  = blockIdx.z;
    int b = bh >> 4, h = bh & 15;
    int tx = threadIdx.x & 31, ty = threadIdx.x >> 5;
#pragma unroll
    for (int r = 0; r < 4; ++r)
        t[ty + 8*r][tx] = g_v[((size_t)(b*SEQ) + s0 + ty + 8*r)*DM + h*DKH + dk0 + tx];
    __syncthreads();
#pragma unroll
    for (int r = 0; r < 4; ++r) {
        int dk = ty + 8*r;
        g_vth[((size_t)bh*DKH + dk0 + dk)*SEQ + s0 + tx] = __float2half(t[tx][dk]);
    }
}

// ============================================================
// Flash attention fp16, causal.  2-pass QK (Q split), 2-pass PV (P split).
// CTA: 128 q-rows, kv tile 64.  8 warps x 16 q-rows.
// ============================================================
#define KSTRB 272                      // 128 fp16 row + 16B pad
#define VSTRB 144                      // 64 fp16 row + 16B pad
#define AQH 0
#define AQL 34816
#define AST0 69632
#define ASTAGE 35840                   // K 17408 + VT 18432
#define AK  0
#define AVT 17408
#define ATTN_SMEM (AST0 + 2*ASTAGE)    // 141312

__global__ __launch_bounds__(256, 1)
void attn_mma(const __half* __restrict__ qh, const __half* __restrict__ ql,
              const __half* __restrict__ kh, const __half* __restrict__ vth,
              float* __restrict__ ctx)
{
    extern __shared__ __align__(128) char asm_[];
    const uint32_t sb = smem_u32(asm_);
    const int qt = (gridDim.x - 1) - blockIdx.x;   // longest CTAs first
    const int bh = blockIdx.y;
    const int tid = threadIdx.x, warp = tid >> 5, lane = tid & 31;
    const int b = bh >> 4, h = bh & 15;

    const __half* qhb = qh + ((size_t)bh*SEQ + qt*128)*DKH;
    const __half* qlb = ql + ((size_t)bh*SEQ + qt*128)*DKH;
    const __half* khb = kh + (size_t)bh*SEQ*DKH;
    const __half* vhb = vth + (size_t)bh*DKH*SEQ;

    for (int i = tid; i < 2048; i += 256) {
        int row = i >> 4, seg = i & 15;
        uint32_t dst = (uint32_t)(row * KSTRB + seg * 16);
        cp_async16(sb + AQH + dst, (const char*)(qhb + (size_t)row*DKH) + seg*16);
        cp_async16(sb + AQL + dst, (const char*)(qlb + (size_t)row*DKH) + seg*16);
    }
    cp_commit();

    auto issue_kv = [&](int kt, int buf) {
        uint32_t st = sb + AST0 + buf * ASTAGE;
        for (int i = tid; i < 1024; i += 256) {
            int row = i >> 4, seg = i & 15;
            cp_async16(st + AK + (uint32_t)(row * KSTRB + seg * 16),
                       (const char*)(khb + ((size_t)(kt*64) + row)*DKH) + seg*16);
        }
        for (int i = tid; i < 1024; i += 256) {
            int row = i >> 3, seg = i & 7;
            cp_async16(st + AVT + (uint32_t)(row * VSTRB + seg * 16),
                       (const char*)(vhb + (size_t)row*SEQ + kt*64) + seg*16);
        }
        cp_commit();
    };

    const int nkt = 2*qt + 2;
    issue_kv(0, 0);

    float o[16][4];
#pragma unroll
    for (int i = 0; i < 16; i++)
#pragma unroll
        for (int j = 0; j < 4; j++) o[i][j] = 0.f;
    float m_[2] = {-1e30f, -1e30f};
    float l_[2] = {0.f, 0.f};

    const float scl = 0.08838834764831845f;
    const int row0g = qt*128 + warp*16 + (lane >> 2);

    const uint32_t a_off = (uint32_t)((warp*16 + (lane & 15)) * KSTRB + (lane >> 4) * 16);
    const uint32_t kb_rowsel = (uint32_t)((((lane >> 3) & 1) * 8 + (lane & 7)));
    const uint32_t kseg = (uint32_t)((lane >> 4) * 16);

    for (int kt = 0; kt < nkt; ++kt) {
        int buf = kt & 1;
        if (kt + 1 < nkt) { issue_kv(kt + 1, buf ^ 1); cp_wait<1>(); }
        else              { cp_wait<0>(); }
        __syncthreads();

        uint32_t st = sb + AST0 + buf * ASTAGE;

        float s_[8][4];
#pragma unroll
        for (int i = 0; i < 8; i++)
#pragma unroll
            for (int j = 0; j < 4; j++) s_[i][j] = 0.f;

#pragma unroll
        for (int ks = 0; ks < 8; ++ks) {
            uint32_t aH[4], aL[4];
            ldsm_x4(aH[0], aH[1], aH[2], aH[3], sb + AQH + a_off + ks*32);
            ldsm_x4(aL[0], aL[1], aL[2], aL[3], sb + AQL + a_off + ks*32);
#pragma unroll
            for (int p = 0; p < 4; ++p) {
                uint32_t kaddr = st + AK + (uint32_t)((p*16 + kb_rowsel) * KSTRB) + ks*32 + kseg;
                uint32_t r0, r1, r2, r3;
                ldsm_x4(r0, r1, r2, r3, kaddr);
                uint32_t bh0[2] = {r0, r2}, bh1[2] = {r1, r3};
                mma_f16(s_[2*p],   aH, bh0);
                mma_f16(s_[2*p+1], aH, bh1);
                mma_f16(s_[2*p],   aL, bh0);
                mma_f16(s_[2*p+1], aL, bh1);
            }
        }

        bool need_mask = (kt*64 + 63) > (qt*128 + warp*16);
#pragma unroll
        for (int nt = 0; nt < 8; ++nt) {
            int colg = kt*64 + nt*8 + (lane & 3)*2;
#pragma unroll
            for (int j = 0; j < 4; ++j) {
                float sv = s_[nt][j] * scl;
                if (need_mask) {
                    int r = row0g + ((j >> 1) << 3);
                    int c = colg + (j & 1);
                    if (c > r) sv = -1e30f;
                }
                s_[nt][j] = sv;
            }
        }

        float corr[2];
#pragma unroll
        for (int r = 0; r < 2; ++r) {
            float mx = m_[r];
#pragma unroll
            for (int nt = 0; nt < 8; ++nt)
                mx = fmaxf(mx, fmaxf(s_[nt][2*r], s_[nt][2*r+1]));
            mx = fmaxf(mx, __shfl_xor_sync(0xffffffffu, mx, 1));
            mx = fmaxf(mx, __shfl_xor_sync(0xffffffffu, mx, 2));
            corr[r] = __expf(m_[r] - mx);
            m_[r] = mx;
            float sum = 0.f;
#pragma unroll
            for (int nt = 0; nt < 8; ++nt) {
                float p0 = __expf(s_[nt][2*r]   - mx);
                float p1 = __expf(s_[nt][2*r+1] - mx);
                s_[nt][2*r] = p0; s_[nt][2*r+1] = p1;
                sum += p0 + p1;
            }
            sum += __shfl_xor_sync(0xffffffffu, sum, 1);
            sum += __shfl_xor_sync(0xffffffffu, sum, 2);
            l_[r] = l_[r]*corr[r] + sum;
        }

        uint32_t pH[8][2], pL[8][2];
#pragma unroll
        for (int nt = 0; nt < 8; ++nt) {
#pragma unroll
            for (int r = 0; r < 2; ++r) {
                float p0 = s_[nt][2*r], p1 = s_[nt][2*r+1];
                __half h0 = __float2half(p0), h1 = __float2half(p1);
                pH[nt][r] = pack_h2(p0, p1);
                pL[nt][r] = pack_h2(p0 - __half2float(h0), p1 - __half2float(h1));
            }
        }

#pragma unroll
        for (int dt = 0; dt < 16; ++dt) {
            o[dt][0] *= corr[0]; o[dt][1] *= corr[0];
            o[dt][2] *= corr[1]; o[dt][3] *= corr[1];
        }

#pragma unroll
        for (int kk = 0; kk < 4; ++kk) {
            uint32_t aP[4]  = {pH[2*kk][0], pH[2*kk][1], pH[2*kk+1][0], pH[2*kk+1][1]};
            uint32_t aPl[4] = {pL[2*kk][0], pL[2*kk][1], pL[2*kk+1][0], pL[2*kk+1][1]};
#pragma unroll
            for (int p = 0; p < 8; ++p) {
                uint32_t vaddr = st + AVT + (uint32_t)((p*16 + kb_rowsel) * VSTRB) + kk*32 + kseg;
                uint32_t r0, r1, r2, r3;
                ldsm_x4(r0, r1, r2, r3, vaddr);
                uint32_t vh0[2] = {r0, r2}, vh1[2] = {r1, r3};
                mma_f16(o[2*p],   aP,  vh0);
                mma_f16(o[2*p+1], aP,  vh1);
                mma_f16(o[2*p],   aPl, vh0);
                mma_f16(o[2*p+1], aPl, vh1);
            }
        }
        __syncthreads();
    }

    float inv0 = 1.0f / l_[0], inv1 = 1.0f / l_[1];
    int r0 = qt*128 + warp*16 + (lane >> 2);
#pragma unroll
    for (int dt = 0; dt < 16; ++dt) {
        int col = h*DKH + dt*8 + (lane & 3)*2;
        *(float2*)&ctx[((size_t)(b*SEQ) + r0)*DM + col] =
            make_float2(o[dt][0]*inv0, o[dt][1]*inv0);
        *(float2*)&ctx[((size_t)(b*SEQ) + r0 + 8)*DM + col] =
            make_float2(o[dt][2]*inv1, o[dt][3]*inv1);
    }
}

// ============================================================
extern "C" void kernel_launch(void* const* d_in, const int* in_sizes, int n_in,
                              void* d_out, int out_size)
{
    const float* x  = (const float*)d_in[0];
    const float* wq = (const float*)d_in[1];
    const float* wk = (const float*)d_in[2];
    const float* wv = (const float*)d_in[3];
    const float* wo = (const float*)d_in[4];
    const float* bo = (const float*)d_in[5];
    float* out = (float*)d_out;

    float *q, *k, *v, *ctx;
    __half *x16, *w16, *c16, *qh, *ql, *kh, *vth;
    cudaGetSymbolAddress((void**)&q,   g_q);
    cudaGetSymbolAddress((void**)&k,   g_k);
    cudaGetSymbolAddress((void**)&v,   g_v);
    cudaGetSymbolAddress((void**)&ctx, g_ctx);
    cudaGetSymbolAddress((void**)&x16, g_x16);
    cudaGetSymbolAddress((void**)&w16, g_w16);
    cudaGetSymbolAddress((void**)&c16, g_c16);
    cudaGetSymbolAddress((void**)&qh,  g_qh);
    cudaGetSymbolAddress((void**)&ql,  g_ql);
    cudaGetSymbolAddress((void**)&kh,  g_kh);
    cudaGetSymbolAddress((void**)&vth, g_vth);

    cudaFuncSetAttribute(gemm_f16<0>, cudaFuncAttributeMaxDynamicSharedMemorySize, GEMM_SMEM);
    cudaFuncSetAttribute(gemm_f16<1>, cudaFuncAttributeMaxDynamicSharedMemorySize, GEMM_SMEM);
    cudaFuncSetAttribute(attn_mma, cudaFuncAttributeMaxDynamicSharedMemorySize, ATTN_SMEM);

    const int NX4 = MTOT*DM/4;
    const int NW4 = DM*DM/4;

    tohalf_kernel<<<NX4/256, 256>>>(x, x16, NX4);
    tohalf_kernel<<<NW4/256, 256>>>(wq, w16 + 0*(size_t)DM*DM, NW4);
    tohalf_kernel<<<NW4/256, 256>>>(wk, w16 + 1*(size_t)DM*DM, NW4);
    tohalf_kernel<<<NW4/256, 256>>>(wv, w16 + 2*(size_t)DM*DM, NW4);
    tohalf_kernel<<<NW4/256, 256>>>(wo, w16 + 3*(size_t)DM*DM, NW4);

    dim3 gg(DM/128, MTOT/128);   // (16, 32)
    gemm_f16<0><<<gg, 256, GEMM_SMEM>>>(x16, w16 + 0*(size_t)DM*DM, nullptr, q);
    gemm_f16<0><<<gg, 256, GEMM_SMEM>>>(x16, w16 + 1*(size_t)DM*DM, nullptr, k);
    gemm_f16<0><<<gg, 256, GEMM_SMEM>>>(x16, w16 + 2*(size_t)DM*DM, nullptr, v);

    rope_split_kernel<<<(BH*SEQ*64 + 255)/256, 256>>>();
    vsplit_kernel<<<dim3(DKH/32, SEQ/32, BH), 256>>>();

    attn_mma<<<dim3(SEQ/128, BH), 256, ATTN_SMEM>>>(qh, ql, kh, vth, ctx);

    tohalf_kernel<<<NX4/256, 256>>>(ctx, c16, NX4);
    gemm_f16<1><<<gg, 256, GEMM_SMEM>>>(c16, w16 + 3*(size_t)DM*DM, bo, out);
}